// round 5
// baseline (speedup 1.0000x reference)
#include <cuda_runtime.h>
#include <cstdint>

// Problem constants (fixed by the dataset)
#define N_TOK 4096     // B*K = 128*32
#define DDIM  1024
#define HDIM  256
#define NEXP  32

// Scratch (device globals; no allocation allowed)
__device__ int   g_cnt[NEXP];
__device__ int   g_list[NEXP * N_TOK];
__device__ float g_hidden[N_TOK * HDIM];
__device__ int   g_nwork;
__device__ int   g_work[256];   // max items = sum ceil(cnt/32) <= 128 + 31 = 159

// ---------------------------------------------------------------------------
// Zero counters
// ---------------------------------------------------------------------------
__global__ void zero_kernel() {
    int t = threadIdx.x;
    if (t < NEXP) g_cnt[t] = 0;
    if (t == 0)  g_nwork = 0;
}

// ---------------------------------------------------------------------------
// Router: one warp per token. logits = x @ Wr^T + br ; argmax (first max wins)
// ---------------------------------------------------------------------------
__global__ __launch_bounds__(256) void router_kernel(
    const float* __restrict__ x,
    const float* __restrict__ rw,
    const float* __restrict__ rb)
{
    int gwarp = (blockIdx.x * blockDim.x + threadIdx.x) >> 5;
    int lane  = threadIdx.x & 31;
    if (gwarp >= N_TOK) return;

    const float4* x4 = (const float4*)(x + (size_t)gwarp * DDIM);

    float best = -1e30f;
    int   bidx = 0;
#pragma unroll 1
    for (int e = 0; e < NEXP; e++) {
        const float4* w4 = (const float4*)(rw + (size_t)e * DDIM);
        float s = 0.f;
#pragma unroll
        for (int k = lane; k < DDIM / 4; k += 32) {
            float4 a = x4[k], b = w4[k];
            s += a.x * b.x + a.y * b.y + a.z * b.z + a.w * b.w;
        }
#pragma unroll
        for (int o = 16; o; o >>= 1) s += __shfl_xor_sync(0xffffffffu, s, o);
        s += rb[e];
        if (s > best) { best = s; bidx = e; }   // strict > : first index wins ties
    }
    if (lane == 0) {
        int pos = atomicAdd(&g_cnt[bidx], 1);
        g_list[bidx * N_TOK + pos] = gwarp;
    }
}

// ---------------------------------------------------------------------------
// Build (expert, row_tile) worklist. Tile height = 32 rows.
// ---------------------------------------------------------------------------
__global__ void build_work_kernel() {
    int e = threadIdx.x;
    if (e < NEXP) {
        int nt = (g_cnt[e] + 31) >> 5;
        if (nt > 0) {
            int pos = atomicAdd(&g_nwork, nt);
            for (int i = 0; i < nt; i++) g_work[pos + i] = (e << 16) | i;
        }
    }
}

// ---------------------------------------------------------------------------
// Gathered SGEMM + bias + ReLU, double-buffered.
//   C[m,n] = relu( sum_k A[tok[m],k] * W[e,k,n] + bias[e,n] )
// Tile: 32 rows x 128 cols, KT = 32. Block 256 threads, 4x4 micro-tile.
// Per K-step: prefetch next tile into registers at loop top (LDG latency
// hidden under 32x16 FFMA), store to alternate smem buffer, ONE barrier.
// ---------------------------------------------------------------------------
template <int KDIM, int NTOTAL>
__global__ __launch_bounds__(256) void moe_gemm_kernel(
    const float* __restrict__ A,     // token-major activations, row stride = KDIM
    const float* __restrict__ W,     // [E, KDIM, NTOTAL]
    const float* __restrict__ Bv,    // [E, NTOTAL]
    float* __restrict__ Out)         // token-major, row stride = NTOTAL
{
    constexpr int NCT    = NTOTAL / 128;   // column tiles of 128
    constexpr int NSTEPS = KDIM / 32;

    __shared__ float As[2][32][36];        // [buf][k][m]; stride 36 -> aligned LDS.128
    __shared__ float Bs[2][32][128];       // [buf][k][n]
    __shared__ int   toks[32];

    const int tid = threadIdx.x;
    const int tx  = tid & 31;              // col group: cols tx*4 .. tx*4+3
    const int ty  = tid >> 5;              // row group: rows ty*4 .. ty*4+3

    // A-tile load mapping: one float4 along k per thread
    const int am = tid >> 3;               // 0..31 row-in-tile
    const int ak = (tid & 7) << 2;         // 0,4,...,28
    // B-tile load mapping: 4 rows (strided by 8), one float4 per thread
    const int bn = (tid & 31) << 2;        // 0,4,...,124
    const int bk = tid >> 5;               // 0..7

    const int nwork = g_nwork;
    const int total = nwork * NCT;

    for (int w = blockIdx.x; w < total; w += gridDim.x) {
        const int item = g_work[w / NCT];
        const int ct   = w - (w / NCT) * NCT;
        const int e    = item >> 16;
        const int r0   = (item & 0xffff) << 5;
        const int cnt  = g_cnt[e];
        const int n0   = ct << 7;

        if (tid < 32) {
            int idx = r0 + tid;
            if (idx >= cnt) idx = cnt - 1;       // clamp (loads safe, stores guarded)
            toks[tid] = g_list[e * N_TOK + idx];
        }
        __syncthreads();

        const float* We     = W + (size_t)e * KDIM * NTOTAL + n0;
        const float* Arow   = A + (size_t)toks[am] * KDIM + ak;

        // ---- prologue: load tile 0 -> regs -> smem buf 0 ----
        float4 pa = *(const float4*)(Arow);
        float4 pb[4];
#pragma unroll
        for (int s = 0; s < 4; s++)
            pb[s] = *(const float4*)(We + (size_t)(bk + s * 8) * NTOTAL + bn);

        As[0][ak + 0][am] = pa.x;
        As[0][ak + 1][am] = pa.y;
        As[0][ak + 2][am] = pa.z;
        As[0][ak + 3][am] = pa.w;
#pragma unroll
        for (int s = 0; s < 4; s++)
            *(float4*)&Bs[0][bk + s * 8][bn] = pb[s];
        __syncthreads();

        float acc[4][4];
#pragma unroll
        for (int i = 0; i < 4; i++)
#pragma unroll
            for (int j = 0; j < 4; j++) acc[i][j] = 0.f;

#pragma unroll 1
        for (int step = 0; step < NSTEPS; step++) {
            const int cur = step & 1;
            const int nxt = cur ^ 1;

            // prefetch next tile into registers (LDGs issue, hidden by FFMA)
            if (step + 1 < NSTEPS) {
                const int k0n = (step + 1) << 5;
                pa = *(const float4*)(Arow + k0n);
#pragma unroll
                for (int s = 0; s < 4; s++)
                    pb[s] = *(const float4*)(We + (size_t)(k0n + bk + s * 8) * NTOTAL + bn);
            }

#pragma unroll
            for (int kk = 0; kk < 32; kk++) {
                float4 a = *(const float4*)&As[cur][kk][ty << 2];  // warp broadcast
                float4 b = *(const float4*)&Bs[cur][kk][tx << 2];  // 4-phase, no conflict
                acc[0][0] += a.x * b.x; acc[0][1] += a.x * b.y;
                acc[0][2] += a.x * b.z; acc[0][3] += a.x * b.w;
                acc[1][0] += a.y * b.x; acc[1][1] += a.y * b.y;
                acc[1][2] += a.y * b.z; acc[1][3] += a.y * b.w;
                acc[2][0] += a.z * b.x; acc[2][1] += a.z * b.y;
                acc[2][2] += a.z * b.z; acc[2][3] += a.z * b.w;
                acc[3][0] += a.w * b.x; acc[3][1] += a.w * b.y;
                acc[3][2] += a.w * b.z; acc[3][3] += a.w * b.w;
            }

            if (step + 1 < NSTEPS) {
                As[nxt][ak + 0][am] = pa.x;
                As[nxt][ak + 1][am] = pa.y;
                As[nxt][ak + 2][am] = pa.z;
                As[nxt][ak + 3][am] = pa.w;
#pragma unroll
                for (int s = 0; s < 4; s++)
                    *(float4*)&Bs[nxt][bk + s * 8][bn] = pb[s];
            }
            __syncthreads();
        }

        // ---- epilogue: bias + ReLU, scatter to token rows ----
        float4 bv = *(const float4*)(Bv + (size_t)e * NTOTAL + n0 + (tx << 2));
#pragma unroll
        for (int i = 0; i < 4; i++) {
            int m = (ty << 2) + i;
            if (r0 + m < cnt) {
                float4 o;
                o.x = fmaxf(acc[i][0] + bv.x, 0.f);
                o.y = fmaxf(acc[i][1] + bv.y, 0.f);
                o.z = fmaxf(acc[i][2] + bv.z, 0.f);
                o.w = fmaxf(acc[i][3] + bv.w, 0.f);
                *(float4*)(Out + (size_t)toks[m] * NTOTAL + n0 + (tx << 2)) = o;
            }
        }
        __syncthreads();   // protect toks/smem before next work item
    }
}

// ---------------------------------------------------------------------------
// Launch
// ---------------------------------------------------------------------------
extern "C" void kernel_launch(void* const* d_in, const int* in_sizes, int n_in,
                              void* d_out, int out_size)
{
    const float* x  = (const float*)d_in[0];  // [N, D]
    const float* rw = (const float*)d_in[1];  // [E, D]
    const float* rb = (const float*)d_in[2];  // [E]
    const float* w1 = (const float*)d_in[3];  // [E, D, H]
    const float* b1 = (const float*)d_in[4];  // [E, H]
    const float* w2 = (const float*)d_in[5];  // [E, H, D]
    const float* b2 = (const float*)d_in[6];  // [E, D]
    float* out = (float*)d_out;               // [N, D]

    float* hidden = nullptr;
    cudaGetSymbolAddress((void**)&hidden, g_hidden);

    zero_kernel<<<1, 64>>>();
    router_kernel<<<N_TOK / 8, 256>>>(x, rw, rb);   // 8 warps/block, 1 token/warp
    build_work_kernel<<<1, 32>>>();
    // layer 1: K=D=1024 -> H=256 (2 col tiles of 128). Max items*NCT = 159*2 = 318.
    moe_gemm_kernel<DDIM, HDIM><<<320, 256>>>(x, w1, b1, hidden);
    // layer 2: K=H=256 -> D=1024 (8 col tiles of 128). Max items*NCT = 159*8 = 1272.
    moe_gemm_kernel<HDIM, DDIM><<<1280, 256>>>(hidden, w2, b2, out);
}